// round 1
// baseline (speedup 1.0000x reference)
#include <cuda_runtime.h>
#include <math.h>

#define K_DIM 7168
#define N_EXP 256
#define BM 128
#define BN 128
#define BK 32
#define BM_P (BM + 4)
#define BN_P (BN + 4)
#define MAX_T 8192

// scratch for logits [T, 256]
__device__ float g_logits[(size_t)MAX_T * N_EXP];

__device__ __forceinline__ unsigned long long pack2(float lo, float hi) {
    unsigned long long r;
    asm("mov.b64 %0, {%1, %2};" : "=l"(r) : "f"(lo), "f"(hi));
    return r;
}
__device__ __forceinline__ void unpack2(unsigned long long v, float &lo, float &hi) {
    asm("mov.b64 {%0, %1}, %2;" : "=f"(lo), "=f"(hi) : "l"(v));
}
// packed fp32x2 FMA (Blackwell sm_100+): d = a*b + d elementwise on 2 floats
__device__ __forceinline__ void fma2(unsigned long long &d, unsigned long long a, unsigned long long b) {
    asm("fma.rn.f32x2 %0, %1, %2, %0;" : "+l"(d) : "l"(a), "l"(b));
}

// ---------------------------------------------------------------------------
// GEMM: logits[t][e] = sum_k x[t][k] * W[e][k], fp32 exact
// 128x128 CTA tile, BK=32, 256 threads, 8x8 microtile via f32x2 pairs
// ---------------------------------------------------------------------------
__global__ __launch_bounds__(256, 1)
void gemm_kernel(const float* __restrict__ X, const float* __restrict__ W, int T) {
    __shared__ float As[BK][BM_P];
    __shared__ float Bs[BK][BN_P];
    const int tid = threadIdx.x;
    const int m0 = blockIdx.x * BM;
    const int n0 = blockIdx.y * BN;
    const int tx = tid & 15;
    const int ty = tid >> 4;

    unsigned long long acc[8][4];
#pragma unroll
    for (int i = 0; i < 8; i++)
#pragma unroll
        for (int j = 0; j < 4; j++) acc[i][j] = 0ULL;

    float4 pa[4], pb[4];
    int lrow[4], lc4[4];
#pragma unroll
    for (int q = 0; q < 4; q++) {
        int lin = tid + q * 256;
        lrow[q] = lin >> 3;   // 0..127
        lc4[q] = lin & 7;     // float4 index within 32-wide k-chunk
    }

    // initial tile load (kt = 0)
#pragma unroll
    for (int q = 0; q < 4; q++) {
        int gr = m0 + lrow[q]; if (gr >= T) gr = T - 1;
        pa[q] = *(const float4*)(X + (size_t)gr * K_DIM + lc4[q] * 4);
        pb[q] = *(const float4*)(W + (size_t)(n0 + lrow[q]) * K_DIM + lc4[q] * 4);
    }
#pragma unroll
    for (int q = 0; q < 4; q++) {
        int kk = lc4[q] * 4;
        As[kk + 0][lrow[q]] = pa[q].x; As[kk + 1][lrow[q]] = pa[q].y;
        As[kk + 2][lrow[q]] = pa[q].z; As[kk + 3][lrow[q]] = pa[q].w;
        Bs[kk + 0][lrow[q]] = pb[q].x; Bs[kk + 1][lrow[q]] = pb[q].y;
        Bs[kk + 2][lrow[q]] = pb[q].z; Bs[kk + 3][lrow[q]] = pb[q].w;
    }

    for (int kt = 0; kt < K_DIM; kt += BK) {
        __syncthreads();
        const int ktn = kt + BK;
        if (ktn < K_DIM) {
            // prefetch next tile into registers (hides DRAM/L2 latency under compute)
#pragma unroll
            for (int q = 0; q < 4; q++) {
                int gr = m0 + lrow[q]; if (gr >= T) gr = T - 1;
                pa[q] = *(const float4*)(X + (size_t)gr * K_DIM + ktn + lc4[q] * 4);
                pb[q] = *(const float4*)(W + (size_t)(n0 + lrow[q]) * K_DIM + ktn + lc4[q] * 4);
            }
        }
#pragma unroll
        for (int k = 0; k < BK; k++) {
            float4 a0 = *(const float4*)&As[k][ty * 8];
            float4 a1 = *(const float4*)&As[k][ty * 8 + 4];
            float4 b0 = *(const float4*)&Bs[k][tx * 8];
            float4 b1 = *(const float4*)&Bs[k][tx * 8 + 4];
            unsigned long long bb0 = pack2(b0.x, b0.y);
            unsigned long long bb1 = pack2(b0.z, b0.w);
            unsigned long long bb2 = pack2(b1.x, b1.y);
            unsigned long long bb3 = pack2(b1.z, b1.w);
            float av[8] = {a0.x, a0.y, a0.z, a0.w, a1.x, a1.y, a1.z, a1.w};
#pragma unroll
            for (int i = 0; i < 8; i++) {
                unsigned long long aa = pack2(av[i], av[i]);
                fma2(acc[i][0], aa, bb0);
                fma2(acc[i][1], aa, bb1);
                fma2(acc[i][2], aa, bb2);
                fma2(acc[i][3], aa, bb3);
            }
        }
        __syncthreads();
        if (ktn < K_DIM) {
#pragma unroll
            for (int q = 0; q < 4; q++) {
                int kk = lc4[q] * 4;
                As[kk + 0][lrow[q]] = pa[q].x; As[kk + 1][lrow[q]] = pa[q].y;
                As[kk + 2][lrow[q]] = pa[q].z; As[kk + 3][lrow[q]] = pa[q].w;
                Bs[kk + 0][lrow[q]] = pb[q].x; Bs[kk + 1][lrow[q]] = pb[q].y;
                Bs[kk + 2][lrow[q]] = pb[q].z; Bs[kk + 3][lrow[q]] = pb[q].w;
            }
        }
    }

    // epilogue: write logits
#pragma unroll
    for (int i = 0; i < 8; i++) {
        int gr = m0 + ty * 8 + i;
        if (gr < T) {
            float f0, f1, f2, f3, f4, f5, f6, f7;
            unpack2(acc[i][0], f0, f1);
            unpack2(acc[i][1], f2, f3);
            unpack2(acc[i][2], f4, f5);
            unpack2(acc[i][3], f6, f7);
            float* dst = g_logits + (size_t)gr * N_EXP + n0 + tx * 8;
            *(float4*)(dst)     = make_float4(f0, f1, f2, f3);
            *(float4*)(dst + 4) = make_float4(f4, f5, f6, f7);
        }
    }
}

// ---------------------------------------------------------------------------
// Router: one warp per token. Lane owns 8 consecutive experts (group = 4 lanes).
// ---------------------------------------------------------------------------
__global__ void router_kernel(const float* __restrict__ bias, float* __restrict__ out, int T) {
    int gwarp = (int)((blockIdx.x * blockDim.x + threadIdx.x) >> 5);
    int lane = threadIdx.x & 31;
    if (gwarp >= T) return;
    const float* lg = g_logits + (size_t)gwarp * N_EXP;
    int e0 = lane * 8;

    float4 l0 = *(const float4*)(lg + e0);
    float4 l1 = *(const float4*)(lg + e0 + 4);
    float4 c0 = *(const float4*)(bias + e0);
    float4 c1 = *(const float4*)(bias + e0 + 4);
    float lv[8] = {l0.x, l0.y, l0.z, l0.w, l1.x, l1.y, l1.z, l1.w};
    float bv8[8] = {c0.x, c0.y, c0.z, c0.w, c1.x, c1.y, c1.z, c1.w};

    float s[8], sc[8], val[8];
#pragma unroll
    for (int j = 0; j < 8; j++) {
        s[j] = 1.0f / (1.0f + expf(-lv[j]));   // sigmoid (pre-bias score)
        sc[j] = s[j] + bv8[j];                 // score_for_choice
    }

    // local top-2 of sc within lane's 8 experts
    float m1 = -1e30f, m2 = -1e30f;
#pragma unroll
    for (int j = 0; j < 8; j++) {
        float v = sc[j];
        if (v > m1) { m2 = m1; m1 = v; }
        else if (v > m2) { m2 = v; }
    }
    // merge top-2 across the 4 lanes of the group (xor 1, xor 2)
#pragma unroll
    for (int off = 1; off <= 2; off <<= 1) {
        float o1 = __shfl_xor_sync(0xffffffffu, m1, off);
        float o2 = __shfl_xor_sync(0xffffffffu, m2, off);
        float n1 = fmaxf(m1, o1);
        float n2 = fmaxf(fminf(m1, o1), fmaxf(m2, o2));
        m1 = n1; m2 = n2;
    }
    float gs = m1 + m2;  // group score (same in all 4 lanes of group)
    int myg = lane >> 2;

    // rank my group among all 8 (tie -> lower group index wins, like top_k)
    int better = 0;
#pragma unroll
    for (int g = 0; g < 8; g++) {
        float og = __shfl_sync(0xffffffffu, gs, g * 4);
        if (og > gs || (og == gs && g < myg)) better++;
    }
    bool selg = (better < 4);
#pragma unroll
    for (int j = 0; j < 8; j++) val[j] = selg ? sc[j] : 0.0f;

    // 8 rounds of warp argmax (value desc, tie -> lower expert index)
    float wsum = 0.0f;
    int sel_i = 0; float sel_w = 0.0f;
#pragma unroll
    for (int r = 0; r < 8; r++) {
        float bv = val[0]; int bi = e0;
#pragma unroll
        for (int j = 1; j < 8; j++) {
            if (val[j] > bv) { bv = val[j]; bi = e0 + j; }
        }
#pragma unroll
        for (int off = 16; off > 0; off >>= 1) {
            float ov = __shfl_xor_sync(0xffffffffu, bv, off);
            int oi = __shfl_xor_sync(0xffffffffu, bi, off);
            if (ov > bv || (ov == bv && oi < bi)) { bv = ov; bi = oi; }
        }
        int owner = bi >> 3;
        float ws = 0.0f;
        if (lane == owner) {
            int jj = bi & 7;
#pragma unroll
            for (int j = 0; j < 8; j++) {
                if (j == jj) { ws = s[j]; val[j] = -1e30f; }
            }
        }
        ws = __shfl_sync(0xffffffffu, ws, owner);
        wsum += ws;
        if (lane == r) { sel_i = bi; sel_w = ws; }
    }
    float norm = 2.5f / (wsum + 1e-20f);
    if (lane < 8) {
        // output layout: [T*8 indices (as float)] then [T*8 weights]
        out[(size_t)gwarp * 8 + lane] = (float)sel_i;
        out[(size_t)T * 8 + (size_t)gwarp * 8 + lane] = sel_w * norm;
    }
}

extern "C" void kernel_launch(void* const* d_in, const int* in_sizes, int n_in,
                              void* d_out, int out_size) {
    const float* X = (const float*)d_in[0];
    const float* W = (const float*)d_in[1];
    const float* bias = (const float*)d_in[2];
    int T = in_sizes[0] / K_DIM;
    if (T > MAX_T) T = MAX_T;

    dim3 grid((T + BM - 1) / BM, N_EXP / BN);
    gemm_kernel<<<grid, 256>>>(X, W, T);

    int blocks = (T * 32 + 255) / 256;
    router_kernel<<<blocks, 256>>>(bias, (float*)d_out, T);
}

// round 4
// speedup vs baseline: 1.3287x; 1.3287x over previous
#include <cuda_runtime.h>
#include <cuda_fp16.h>
#include <cstdint>
#include <math.h>

#define K_DIM 7168
#define N_EXP 256
#define T_TOK 8192
#define BK 32
#define NC (K_DIM / BK)   // 224
#define BM 64
#define CS 8              // chunks per accumulation segment

// ---------------- device scratch ----------------
__device__ float g_logits[(size_t)T_TOK * N_EXP];
__device__ __half g_whf[(size_t)N_EXP * K_DIM];   // 1024*W high half
__device__ __half g_wlf[(size_t)N_EXP * K_DIM];   // 1024*W low  half

// ---------------- helpers ----------------
__device__ __forceinline__ uint32_t smem_u32(const void* p) {
    uint32_t a;
    asm("{ .reg .u64 t; cvta.to.shared.u64 t, %1; cvt.u32.u64 %0, t; }" : "=r"(a) : "l"(p));
    return a;
}
__device__ __forceinline__ void cp_async16(uint32_t s, const void* g) {
    asm volatile("cp.async.cg.shared.global [%0], [%1], 16;" :: "r"(s), "l"(g) : "memory");
}
#define CP_COMMIT() asm volatile("cp.async.commit_group;" ::: "memory")
#define CP_WAIT(n)  asm volatile("cp.async.wait_group %0;" :: "n"(n) : "memory")

__device__ __forceinline__ void ldm4(uint32_t r[4], uint32_t addr) {
    asm volatile("ldmatrix.sync.aligned.m8n8.x4.shared.b16 {%0,%1,%2,%3}, [%4];"
        : "=r"(r[0]), "=r"(r[1]), "=r"(r[2]), "=r"(r[3]) : "r"(addr));
}
__device__ __forceinline__ void mma16816(float c[4], const uint32_t a[4], uint32_t b0, uint32_t b1) {
    asm volatile("mma.sync.aligned.m16n8k16.row.col.f32.f16.f16.f32 "
        "{%0,%1,%2,%3}, {%4,%5,%6,%7}, {%8,%9}, {%0,%1,%2,%3};"
        : "+f"(c[0]), "+f"(c[1]), "+f"(c[2]), "+f"(c[3])
        : "r"(a[0]), "r"(a[1]), "r"(a[2]), "r"(a[3]), "r"(b0), "r"(b1));
}
#define STS128U(addr, r0, r1, r2, r3) \
    asm volatile("st.shared.v4.b32 [%0], {%1, %2, %3, %4};" \
        :: "r"(addr), "r"(r0), "r"(r1), "r"(r2), "r"(r3) : "memory")

__device__ __forceinline__ uint32_t packh(__half a, __half b) {
    return (uint32_t)__half_as_ushort(a) | ((uint32_t)__half_as_ushort(b) << 16);
}

__device__ __forceinline__ void sts_cvt(uint32_t ah, uint32_t al, float4 v0, float4 v1) {
    float xs[8] = {v0.x, v0.y, v0.z, v0.w, v1.x, v1.y, v1.z, v1.w};
    uint32_t hu[4], lu[4];
#pragma unroll
    for (int p = 0; p < 4; p++) {
        __half h0 = __float2half_rn(xs[2 * p]);
        __half h1 = __float2half_rn(xs[2 * p + 1]);
        __half l0 = __float2half_rn(xs[2 * p] - __half2float(h0));
        __half l1 = __float2half_rn(xs[2 * p + 1] - __half2float(h1));
        hu[p] = packh(h0, h1);
        lu[p] = packh(l0, l1);
    }
    STS128U(ah, hu[0], hu[1], hu[2], hu[3]);
    STS128U(al, lu[0], lu[1], lu[2], lu[3]);
}

// ---------------------------------------------------------------------------
// W split: scale by 1024 (exact), split to fp16 hi/lo
// ---------------------------------------------------------------------------
__global__ void wsplit_kernel(const float* __restrict__ W) {
    int i = blockIdx.x * 256 + threadIdx.x;
    float4 v = ((const float4*)W)[i];
    float x0 = v.x * 1024.0f, x1 = v.y * 1024.0f, x2 = v.z * 1024.0f, x3 = v.w * 1024.0f;
    __half h0 = __float2half_rn(x0), h1 = __float2half_rn(x1);
    __half h2 = __float2half_rn(x2), h3 = __float2half_rn(x3);
    __half l0 = __float2half_rn(x0 - __half2float(h0));
    __half l1 = __float2half_rn(x1 - __half2float(h1));
    __half l2 = __float2half_rn(x2 - __half2float(h2));
    __half l3 = __float2half_rn(x3 - __half2float(h3));
    uint2 ph, pl;
    ph.x = packh(h0, h1); ph.y = packh(h2, h3);
    pl.x = packh(l0, l1); pl.y = packh(l2, l3);
    ((uint2*)g_whf)[i] = ph;
    ((uint2*)g_wlf)[i] = pl;
}

// ---------------------------------------------------------------------------
// GEMM: logits = X . W^T via fp16x3 mma.sync, segmented fp32 master accum.
// CTA tile M=64, N=256, BK=32.
// ---------------------------------------------------------------------------
#define SMEM_DYN 143360

__global__ __launch_bounds__(256, 1)
void gemm_f16_kernel(const float* __restrict__ X) {
    extern __shared__ __half smh[];
    const uint32_t sbase = smem_u32(smh);
    const int tid = threadIdx.x, wid = tid >> 5, lane = tid & 31;
    const int m0 = blockIdx.x * BM;
    const int wm = wid & 1, wn = wid >> 1;

    const uint32_t AH0 = sbase;              // 2 stages x 5120B
    const uint32_t AL0 = sbase + 10240;
    const uint32_t BH0 = sbase + 20480;      // 3 stages x 20480B
    const uint32_t BL0 = sbase + 81920;

    const int xrow = tid >> 2, xseg = tid & 3;
    const float* xp = X + (size_t)(m0 + xrow) * K_DIM + xseg * 8;
    const uint32_t aoff = (uint32_t)(xrow * 80 + xseg * 16);

    uint32_t bdst[4];
    const __half* bhp[4];
    const __half* blp[4];
#pragma unroll
    for (int q = 0; q < 4; q++) {
        int idx = tid + q * 256;
        int r = idx >> 2, s = idx & 3;
        bdst[q] = (uint32_t)(r * 80 + s * 16);
        bhp[q] = g_whf + (size_t)r * K_DIM + s * 8;
        blp[q] = g_wlf + (size_t)r * K_DIM + s * 8;
    }

    const uint32_t baseA = (uint32_t)((wm * 32 + (lane & 15)) * 80 + (lane >> 4) * 16);
    const uint32_t baseB = (uint32_t)((wn * 64 + (lane & 15)) * 80 + (lane >> 4) * 16);

    float acc[2][8][4];     // HMMA segment accumulators
    float mst[2][8][4];     // fp32 master accumulators (IEEE rn adds)
#pragma unroll
    for (int i = 0; i < 2; i++)
#pragma unroll
        for (int j = 0; j < 8; j++)
#pragma unroll
            for (int d = 0; d < 4; d++) { acc[i][j][d] = 0.0f; mst[i][j][d] = 0.0f; }

#pragma unroll
    for (int t = 0; t < 2; t++) {
#pragma unroll
        for (int q = 0; q < 4; q++) {
            cp_async16(BH0 + t * 20480 + bdst[q], bhp[q] + t * BK);
            cp_async16(BL0 + t * 20480 + bdst[q], blp[q] + t * BK);
        }
        CP_COMMIT();
    }
    {
        float4 v0 = *(const float4*)(xp);
        float4 v1 = *(const float4*)(xp + 4);
        sts_cvt(AH0 + aoff, AL0 + aoff, v0, v1);
    }
    float4 xr0 = *(const float4*)(xp + BK);
    float4 xr1 = *(const float4*)(xp + BK + 4);

    for (int c = 0; c < NC; c++) {
        const uint32_t sa = (uint32_t)(c & 1) * 5120;
        const uint32_t sb3 = (uint32_t)(c % 3) * 20480;

        if (c + 2 < NC) {
            const uint32_t st = (uint32_t)((c + 2) % 3) * 20480;
#pragma unroll
            for (int q = 0; q < 4; q++) {
                cp_async16(BH0 + st + bdst[q], bhp[q] + (c + 2) * BK);
                cp_async16(BL0 + st + bdst[q], blp[q] + (c + 2) * BK);
            }
            CP_COMMIT();
        }
        if (c + 1 < NC) {
            const uint32_t sa2 = (uint32_t)((c + 1) & 1) * 5120;
            sts_cvt(AH0 + sa2 + aoff, AL0 + sa2 + aoff, xr0, xr1);
        }
        if (c + 2 < NC) {
            xr0 = *(const float4*)(xp + (c + 2) * BK);
            xr1 = *(const float4*)(xp + (c + 2) * BK + 4);
        }
        if (c + 2 < NC) { CP_WAIT(2); }
        else if (c + 1 < NC) { CP_WAIT(1); }
        else { CP_WAIT(0); }
        __syncthreads();

#pragma unroll
        for (int k0 = 0; k0 <= 32; k0 += 32) {
            uint32_t ah[2][4], al[2][4];
            ldm4(ah[0], AH0 + sa + baseA + k0);
            ldm4(ah[1], AH0 + sa + baseA + 1280 + k0);
            ldm4(al[0], AL0 + sa + baseA + k0);
            ldm4(al[1], AL0 + sa + baseA + 1280 + k0);
#pragma unroll
            for (int jj = 0; jj < 4; jj++) {
                uint32_t bh[4], bl[4];
                ldm4(bh, BH0 + sb3 + baseB + jj * 1280 + k0);
                ldm4(bl, BL0 + sb3 + baseB + jj * 1280 + k0);
                mma16816(acc[0][2 * jj],     ah[0], bh[0], bh[2]);
                mma16816(acc[0][2 * jj + 1], ah[0], bh[1], bh[3]);
                mma16816(acc[1][2 * jj],     ah[1], bh[0], bh[2]);
                mma16816(acc[1][2 * jj + 1], ah[1], bh[1], bh[3]);
                mma16816(acc[0][2 * jj],     ah[0], bl[0], bl[2]);
                mma16816(acc[0][2 * jj + 1], ah[0], bl[1], bl[3]);
                mma16816(acc[1][2 * jj],     ah[1], bl[0], bl[2]);
                mma16816(acc[1][2 * jj + 1], ah[1], bl[1], bl[3]);
                mma16816(acc[0][2 * jj],     al[0], bh[0], bh[2]);
                mma16816(acc[0][2 * jj + 1], al[0], bh[1], bh[3]);
                mma16816(acc[1][2 * jj],     al[1], bh[0], bh[2]);
                mma16816(acc[1][2 * jj + 1], al[1], bh[1], bh[3]);
            }
        }
        // drain HMMA accumulators into fp32 masters every CS chunks
        if ((c & (CS - 1)) == (CS - 1)) {
#pragma unroll
            for (int i = 0; i < 2; i++)
#pragma unroll
                for (int j = 0; j < 8; j++)
#pragma unroll
                    for (int d = 0; d < 4; d++) {
                        mst[i][j][d] += acc[i][j][d];
                        acc[i][j][d] = 0.0f;
                    }
        }
        __syncthreads();
    }

    // epilogue: undo the 1024 scale, write logits
    const float scl = 1.0f / 1024.0f;
#pragma unroll
    for (int i = 0; i < 2; i++) {
#pragma unroll
        for (int j = 0; j < 8; j++) {
            int row = m0 + wm * 32 + i * 16 + (lane >> 2);
            int col = wn * 64 + j * 8 + (lane & 3) * 2;
            float2 v0 = make_float2(mst[i][j][0] * scl, mst[i][j][1] * scl);
            float2 v1 = make_float2(mst[i][j][2] * scl, mst[i][j][3] * scl);
            *(float2*)(g_logits + (size_t)row * N_EXP + col) = v0;
            *(float2*)(g_logits + (size_t)(row + 8) * N_EXP + col) = v1;
        }
    }
}

// ---------------------------------------------------------------------------
// Router: one warp per token (verified in round 1)
// ---------------------------------------------------------------------------
__global__ void router_kernel(const float* __restrict__ bias, float* __restrict__ out, int T) {
    int gwarp = (int)((blockIdx.x * blockDim.x + threadIdx.x) >> 5);
    int lane = threadIdx.x & 31;
    if (gwarp >= T) return;
    const float* lg = g_logits + (size_t)gwarp * N_EXP;
    int e0 = lane * 8;

    float4 l0 = *(const float4*)(lg + e0);
    float4 l1 = *(const float4*)(lg + e0 + 4);
    float4 c0 = *(const float4*)(bias + e0);
    float4 c1 = *(const float4*)(bias + e0 + 4);
    float lv[8] = {l0.x, l0.y, l0.z, l0.w, l1.x, l1.y, l1.z, l1.w};
    float bv8[8] = {c0.x, c0.y, c0.z, c0.w, c1.x, c1.y, c1.z, c1.w};

    float s[8], sc[8], val[8];
#pragma unroll
    for (int j = 0; j < 8; j++) {
        s[j] = 1.0f / (1.0f + expf(-lv[j]));
        sc[j] = s[j] + bv8[j];
    }
    float m1 = -1e30f, m2 = -1e30f;
#pragma unroll
    for (int j = 0; j < 8; j++) {
        float v = sc[j];
        if (v > m1) { m2 = m1; m1 = v; }
        else if (v > m2) { m2 = v; }
    }
#pragma unroll
    for (int off = 1; off <= 2; off <<= 1) {
        float o1 = __shfl_xor_sync(0xffffffffu, m1, off);
        float o2 = __shfl_xor_sync(0xffffffffu, m2, off);
        float n1 = fmaxf(m1, o1);
        float n2 = fmaxf(fminf(m1, o1), fmaxf(m2, o2));
        m1 = n1; m2 = n2;
    }
    float gs = m1 + m2;
    int myg = lane >> 2;
    int better = 0;
#pragma unroll
    for (int g = 0; g < 8; g++) {
        float og = __shfl_sync(0xffffffffu, gs, g * 4);
        if (og > gs || (og == gs && g < myg)) better++;
    }
    bool selg = (better < 4);
#pragma unroll
    for (int j = 0; j < 8; j++) val[j] = selg ? sc[j] : 0.0f;

    float wsum = 0.0f;
    int sel_i = 0; float sel_w = 0.0f;
#pragma unroll
    for (int r = 0; r < 8; r++) {
        float bv = val[0]; int bi = e0;
#pragma unroll
        for (int j = 1; j < 8; j++) {
            if (val[j] > bv) { bv = val[j]; bi = e0 + j; }
        }
#pragma unroll
        for (int off = 16; off > 0; off >>= 1) {
            float ov = __shfl_xor_sync(0xffffffffu, bv, off);
            int oi = __shfl_xor_sync(0xffffffffu, bi, off);
            if (ov > bv || (ov == bv && oi < bi)) { bv = ov; bi = oi; }
        }
        int owner = bi >> 3;
        float ws = 0.0f;
        if (lane == owner) {
            int jj = bi & 7;
#pragma unroll
            for (int j = 0; j < 8; j++) {
                if (j == jj) { ws = s[j]; val[j] = -1e30f; }
            }
        }
        ws = __shfl_sync(0xffffffffu, ws, owner);
        wsum += ws;
        if (lane == r) { sel_i = bi; sel_w = ws; }
    }
    float norm = 2.5f / (wsum + 1e-20f);
    if (lane < 8) {
        out[(size_t)gwarp * 8 + lane] = (float)sel_i;
        out[(size_t)T * 8 + (size_t)gwarp * 8 + lane] = sel_w * norm;
    }
}

extern "C" void kernel_launch(void* const* d_in, const int* in_sizes, int n_in,
                              void* d_out, int out_size) {
    const float* X = (const float*)d_in[0];
    const float* W = (const float*)d_in[1];
    const float* bias = (const float*)d_in[2];
    int T = in_sizes[0] / K_DIM;
    if (T > T_TOK) T = T_TOK;

    cudaFuncSetAttribute(gemm_f16_kernel, cudaFuncAttributeMaxDynamicSharedMemorySize, SMEM_DYN);

    wsplit_kernel<<<(N_EXP * K_DIM / 4) / 256, 256>>>(W);
    gemm_f16_kernel<<<T / BM, 256, SMEM_DYN>>>(X);
    router_kernel<<<(T * 32 + 255) / 256, 256>>>(bias, (float*)d_out, T);
}

// round 6
// speedup vs baseline: 2.2465x; 1.6907x over previous
#include <cuda_runtime.h>
#include <cuda_fp16.h>
#include <cstdint>
#include <math.h>

#define K_DIM 7168
#define N_EXP 256
#define T_TOK 8192
#define BK 32
#define NC (K_DIM / BK)   // 224
#define CS 8

// ---------------- device scratch ----------------
__device__ float g_logits[(size_t)T_TOK * N_EXP];
__device__ __half g_whf[(size_t)N_EXP * K_DIM];   // 1024*W high half
__device__ __half g_wlf[(size_t)N_EXP * K_DIM];   // 1024*W low  half

// ---------------- helpers ----------------
__device__ __forceinline__ uint32_t smem_u32(const void* p) {
    uint32_t a;
    asm("{ .reg .u64 t; cvta.to.shared.u64 t, %1; cvt.u32.u64 %0, t; }" : "=r"(a) : "l"(p));
    return a;
}
__device__ __forceinline__ void cp_async16(uint32_t s, const void* g) {
    asm volatile("cp.async.cg.shared.global [%0], [%1], 16;" :: "r"(s), "l"(g) : "memory");
}
#define CP_COMMIT() asm volatile("cp.async.commit_group;" ::: "memory")
#define CP_WAIT(n)  asm volatile("cp.async.wait_group %0;" :: "n"(n) : "memory")

__device__ __forceinline__ void ldm4(uint32_t r[4], uint32_t addr) {
    asm volatile("ldmatrix.sync.aligned.m8n8.x4.shared.b16 {%0,%1,%2,%3}, [%4];"
        : "=r"(r[0]), "=r"(r[1]), "=r"(r[2]), "=r"(r[3]) : "r"(addr));
}
// fp32-accumulator HMMA
__device__ __forceinline__ void mma_f32(float c[4], const uint32_t a[4], uint32_t b0, uint32_t b1) {
    asm volatile("mma.sync.aligned.m16n8k16.row.col.f32.f16.f16.f32 "
        "{%0,%1,%2,%3}, {%4,%5,%6,%7}, {%8,%9}, {%0,%1,%2,%3};"
        : "+f"(c[0]), "+f"(c[1]), "+f"(c[2]), "+f"(c[3])
        : "r"(a[0]), "r"(a[1]), "r"(a[2]), "r"(a[3]), "r"(b0), "r"(b1));
}
// fp16-accumulator HMMA (C/D = 2 x f16x2 regs)
__device__ __forceinline__ void mma_f16(uint32_t c[2], const uint32_t a[4], uint32_t b0, uint32_t b1) {
    asm volatile("mma.sync.aligned.m16n8k16.row.col.f16.f16.f16.f16 "
        "{%0,%1}, {%2,%3,%4,%5}, {%6,%7}, {%0,%1};"
        : "+r"(c[0]), "+r"(c[1])
        : "r"(a[0]), "r"(a[1]), "r"(a[2]), "r"(a[3]), "r"(b0), "r"(b1));
}
#define STS128U(addr, r0, r1, r2, r3) \
    asm volatile("st.shared.v4.b32 [%0], {%1, %2, %3, %4};" \
        :: "r"(addr), "r"(r0), "r"(r1), "r"(r2), "r"(r3) : "memory")

__device__ __forceinline__ uint32_t packh(__half a, __half b) {
    return (uint32_t)__half_as_ushort(a) | ((uint32_t)__half_as_ushort(b) << 16);
}

__device__ __forceinline__ void sts_cvt(uint32_t ah, uint32_t al, float4 v0, float4 v1) {
    float xs[8] = {v0.x, v0.y, v0.z, v0.w, v1.x, v1.y, v1.z, v1.w};
    uint32_t hu[4], lu[4];
#pragma unroll
    for (int p = 0; p < 4; p++) {
        __half h0 = __float2half_rn(xs[2 * p]);
        __half h1 = __float2half_rn(xs[2 * p + 1]);
        __half l0 = __float2half_rn(xs[2 * p] - __half2float(h0));
        __half l1 = __float2half_rn(xs[2 * p + 1] - __half2float(h1));
        hu[p] = packh(h0, h1);
        lu[p] = packh(l0, l1);
    }
    STS128U(ah, hu[0], hu[1], hu[2], hu[3]);
    STS128U(al, lu[0], lu[1], lu[2], lu[3]);
}

// ---------------------------------------------------------------------------
// W split: scale by 1024 (exact), split to fp16 hi/lo
// ---------------------------------------------------------------------------
__global__ void wsplit_kernel(const float* __restrict__ W) {
    int i = blockIdx.x * 256 + threadIdx.x;
    float4 v = ((const float4*)W)[i];
    float x0 = v.x * 1024.0f, x1 = v.y * 1024.0f, x2 = v.z * 1024.0f, x3 = v.w * 1024.0f;
    __half h0 = __float2half_rn(x0), h1 = __float2half_rn(x1);
    __half h2 = __float2half_rn(x2), h3 = __float2half_rn(x3);
    __half l0 = __float2half_rn(x0 - __half2float(h0));
    __half l1 = __float2half_rn(x1 - __half2float(h1));
    __half l2 = __float2half_rn(x2 - __half2float(h2));
    __half l3 = __float2half_rn(x3 - __half2float(h3));
    uint2 ph, pl;
    ph.x = packh(h0, h1); ph.y = packh(h2, h3);
    pl.x = packh(l0, l1); pl.y = packh(l2, l3);
    ((uint2*)g_whf)[i] = ph;
    ((uint2*)g_wlf)[i] = pl;
}

// ---------------------------------------------------------------------------
// GEMM: M=128 x N=128 CTA tile, 512 threads (16 warps, m16 x n64 each).
// hh product: fp32-accum HMMA, drained every CS chunks.
// low products (xh*wl + xl*wh): shared fp16-accum HMMA, drained every chunk.
// smem: AH[2]|AL[2] stages 10240B each, BH[3]|BL[3] stages 10240B each.
// ---------------------------------------------------------------------------
#define ST_SZ 10240
#define SMEM_DYN (4 * ST_SZ + 6 * ST_SZ)   // 102400

__global__ __launch_bounds__(512, 1)
void gemm_f16_kernel(const float* __restrict__ X) {
    extern __shared__ __half smh[];
    const uint32_t sbase = smem_u32(smh);
    const int tid = threadIdx.x, wid = tid >> 5, lane = tid & 31;
    const int m0 = blockIdx.x * 128, n0 = blockIdx.y * 128;
    const int wm = wid & 7, wn = wid >> 3;

    const uint32_t AH0 = sbase;                 // 2 stages
    const uint32_t AL0 = sbase + 2 * ST_SZ;     // 2 stages
    const uint32_t BH0 = sbase + 4 * ST_SZ;     // 3 stages
    const uint32_t BL0 = sbase + 7 * ST_SZ;     // 3 stages

    // X load mapping: 4 threads/row, 8 floats each (128 rows)
    const int xrow = tid >> 2, xseg = tid & 3;
    const float* xp = X + (size_t)(m0 + xrow) * K_DIM + xseg * 8;
    const uint32_t aoff = (uint32_t)(xrow * 80 + xseg * 16);

    // B cp.async mapping: 1 x 16B per thread per (h|l) per chunk (128 rows x 64B)
    const int brow = tid >> 2, bseg = tid & 3;
    const uint32_t bdst = (uint32_t)(brow * 80 + bseg * 16);
    const __half* bhp = g_whf + (size_t)(n0 + brow) * K_DIM + bseg * 8;
    const __half* blp = g_wlf + (size_t)(n0 + brow) * K_DIM + bseg * 8;

    const uint32_t baseA = (uint32_t)((wm * 16 + (lane & 15)) * 80 + (lane >> 4) * 16);
    const uint32_t baseB = (uint32_t)((wn * 64 + (lane & 15)) * 80 + (lane >> 4) * 16);

    float accHi[8][4];      // hh HMMA segment accumulators (fp32)
    uint32_t accLo[8][2];   // low-product fp16 accumulators
    float mst[8][4];        // fp32 masters
#pragma unroll
    for (int p = 0; p < 8; p++) {
#pragma unroll
        for (int d = 0; d < 4; d++) { accHi[p][d] = 0.0f; mst[p][d] = 0.0f; }
        accLo[p][0] = 0u; accLo[p][1] = 0u;
    }

    // prologue: B0, B1 in flight
#pragma unroll
    for (int t = 0; t < 2; t++) {
        cp_async16(BH0 + t * ST_SZ + bdst, bhp + t * BK);
        cp_async16(BL0 + t * ST_SZ + bdst, blp + t * BK);
        CP_COMMIT();
    }
    // X0 -> A stage 0; X1 -> regs
    {
        float4 v0 = *(const float4*)(xp);
        float4 v1 = *(const float4*)(xp + 4);
        sts_cvt(AH0 + aoff, AL0 + aoff, v0, v1);
    }
    float4 xr0 = *(const float4*)(xp + BK);
    float4 xr1 = *(const float4*)(xp + BK + 4);

    for (int c = 0; c < NC; c++) {
        const uint32_t sa = (uint32_t)(c & 1) * ST_SZ;
        const uint32_t sb = (uint32_t)(c % 3) * ST_SZ;

        if (c + 2 < NC) {
            const uint32_t st = (uint32_t)((c + 2) % 3) * ST_SZ;
            cp_async16(BH0 + st + bdst, bhp + (c + 2) * BK);
            cp_async16(BL0 + st + bdst, blp + (c + 2) * BK);
            CP_COMMIT();
        }
        if (c + 1 < NC) {
            const uint32_t sa2 = (uint32_t)((c + 1) & 1) * ST_SZ;
            sts_cvt(AH0 + sa2 + aoff, AL0 + sa2 + aoff, xr0, xr1);
        }
        if (c + 2 < NC) {
            xr0 = *(const float4*)(xp + (c + 2) * BK);
            xr1 = *(const float4*)(xp + (c + 2) * BK + 4);
        }
        if (c + 2 < NC) { CP_WAIT(2); }
        else if (c + 1 < NC) { CP_WAIT(1); }
        else { CP_WAIT(0); }
        __syncthreads();

#pragma unroll
        for (int k0 = 0; k0 <= 32; k0 += 32) {
            uint32_t ah[4], al[4];
            ldm4(ah, AH0 + sa + baseA + k0);
            ldm4(al, AL0 + sa + baseA + k0);
#pragma unroll
            for (int jj = 0; jj < 4; jj++) {
                uint32_t bh[4], bl[4];
                ldm4(bh, BH0 + sb + baseB + jj * 1280 + k0);
                ldm4(bl, BL0 + sb + baseB + jj * 1280 + k0);
                // hh -> fp32 accum
                mma_f32(accHi[2 * jj],     ah, bh[0], bh[2]);
                mma_f32(accHi[2 * jj + 1], ah, bh[1], bh[3]);
                // xh*wl and xl*wh -> shared fp16 accum
                mma_f16(accLo[2 * jj],     ah, bl[0], bl[2]);
                mma_f16(accLo[2 * jj + 1], ah, bl[1], bl[3]);
                mma_f16(accLo[2 * jj],     al, bh[0], bh[2]);
                mma_f16(accLo[2 * jj + 1], al, bh[1], bh[3]);
            }
        }
        // drain fp16 low accumulators every chunk
#pragma unroll
        for (int p = 0; p < 8; p++) {
            float2 f0 = __half22float2(*(__half2*)&accLo[p][0]);
            float2 f1 = __half22float2(*(__half2*)&accLo[p][1]);
            mst[p][0] += f0.x; mst[p][1] += f0.y;
            mst[p][2] += f1.x; mst[p][3] += f1.y;
            accLo[p][0] = 0u; accLo[p][1] = 0u;
        }
        // drain fp32 hh accumulators every CS chunks
        if ((c & (CS - 1)) == (CS - 1)) {
#pragma unroll
            for (int p = 0; p < 8; p++)
#pragma unroll
                for (int d = 0; d < 4; d++) {
                    mst[p][d] += accHi[p][d];
                    accHi[p][d] = 0.0f;
                }
        }
        __syncthreads();
    }

    // epilogue: undo the 1024 scale, write logits
    const float scl = 1.0f / 1024.0f;
#pragma unroll
    for (int jj = 0; jj < 4; jj++) {
#pragma unroll
        for (int h = 0; h < 2; h++) {
            int p = 2 * jj + h;
            int row = m0 + wm * 16 + (lane >> 2);
            int col = n0 + wn * 64 + jj * 16 + h * 8 + (lane & 3) * 2;
            *(float2*)(g_logits + (size_t)row * N_EXP + col) =
                make_float2(mst[p][0] * scl, mst[p][1] * scl);
            *(float2*)(g_logits + (size_t)(row + 8) * N_EXP + col) =
                make_float2(mst[p][2] * scl, mst[p][3] * scl);
        }
    }
}

// ---------------------------------------------------------------------------
// Router: one warp per token (verified)
// ---------------------------------------------------------------------------
__global__ void router_kernel(const float* __restrict__ bias, float* __restrict__ out, int T) {
    int gwarp = (int)((blockIdx.x * blockDim.x + threadIdx.x) >> 5);
    int lane = threadIdx.x & 31;
    if (gwarp >= T) return;
    const float* lg = g_logits + (size_t)gwarp * N_EXP;
    int e0 = lane * 8;

    float4 l0 = *(const float4*)(lg + e0);
    float4 l1 = *(const float4*)(lg + e0 + 4);
    float4 c0 = *(const float4*)(bias + e0);
    float4 c1 = *(const float4*)(bias + e0 + 4);
    float lv[8] = {l0.x, l0.y, l0.z, l0.w, l1.x, l1.y, l1.z, l1.w};
    float bv8[8] = {c0.x, c0.y, c0.z, c0.w, c1.x, c1.y, c1.z, c1.w};

    float s[8], sc[8], val[8];
#pragma unroll
    for (int j = 0; j < 8; j++) {
        s[j] = 1.0f / (1.0f + expf(-lv[j]));
        sc[j] = s[j] + bv8[j];
    }
    float m1 = -1e30f, m2 = -1e30f;
#pragma unroll
    for (int j = 0; j < 8; j++) {
        float v = sc[j];
        if (v > m1) { m2 = m1; m1 = v; }
        else if (v > m2) { m2 = v; }
    }
#pragma unroll
    for (int off = 1; off <= 2; off <<= 1) {
        float o1 = __shfl_xor_sync(0xffffffffu, m1, off);
        float o2 = __shfl_xor_sync(0xffffffffu, m2, off);
        float n1 = fmaxf(m1, o1);
        float n2 = fmaxf(fminf(m1, o1), fmaxf(m2, o2));
        m1 = n1; m2 = n2;
    }
    float gs = m1 + m2;
    int myg = lane >> 2;
    int better = 0;
#pragma unroll
    for (int g = 0; g < 8; g++) {
        float og = __shfl_sync(0xffffffffu, gs, g * 4);
        if (og > gs || (og == gs && g < myg)) better++;
    }
    bool selg = (better < 4);
#pragma unroll
    for (int j = 0; j < 8; j++) val[j] = selg ? sc[j] : 0.0f;

    float wsum = 0.0f;
    int sel_i = 0; float sel_w = 0.0f;
#pragma unroll
    for (int r = 0; r < 8; r++) {
        float bv = val[0]; int bi = e0;
#pragma unroll
        for (int j = 1; j < 8; j++) {
            if (val[j] > bv) { bv = val[j]; bi = e0 + j; }
        }
#pragma unroll
        for (int off = 16; off > 0; off >>= 1) {
            float ov = __shfl_xor_sync(0xffffffffu, bv, off);
            int oi = __shfl_xor_sync(0xffffffffu, bi, off);
            if (ov > bv || (ov == bv && oi < bi)) { bv = ov; bi = oi; }
        }
        int owner = bi >> 3;
        float ws = 0.0f;
        if (lane == owner) {
            int jj = bi & 7;
#pragma unroll
            for (int j = 0; j < 8; j++) {
                if (j == jj) { ws = s[j]; val[j] = -1e30f; }
            }
        }
        ws = __shfl_sync(0xffffffffu, ws, owner);
        wsum += ws;
        if (lane == r) { sel_i = bi; sel_w = ws; }
    }
    float norm = 2.5f / (wsum + 1e-20f);
    if (lane < 8) {
        out[(size_t)gwarp * 8 + lane] = (float)sel_i;
        out[(size_t)T * 8 + (size_t)gwarp * 8 + lane] = sel_w * norm;
    }
}

extern "C" void kernel_launch(void* const* d_in, const int* in_sizes, int n_in,
                              void* d_out, int out_size) {
    const float* X = (const float*)d_in[0];
    const float* W = (const float*)d_in[1];
    const float* bias = (const float*)d_in[2];
    int T = in_sizes[0] / K_DIM;
    if (T > T_TOK) T = T_TOK;

    cudaFuncSetAttribute(gemm_f16_kernel, cudaFuncAttributeMaxDynamicSharedMemorySize, SMEM_DYN);

    wsplit_kernel<<<(N_EXP * K_DIM / 4) / 256, 256>>>(W);
    dim3 grid(T / 128, N_EXP / 128);
    gemm_f16_kernel<<<grid, 512, SMEM_DYN>>>(X);
    router_kernel<<<(T * 32 + 255) / 256, 256>>>(bias, (float*)d_out, T);
}